// round 2
// baseline (speedup 1.0000x reference)
#include <cuda_runtime.h>
#include <cstdint>

#define TT 512
#define BB 128
#define HH 512
#define GG (3*HH)   // 1536

typedef unsigned long long ull;

// ---------------- device globals (scratch; no cudaMalloc allowed) ----------
__device__ float    g_xW[(size_t)TT*BB*GG];   // [T,B,3H] input-side projections
__device__ int      g_kind;                    // resets dtype: 0=i32, 1=u8, 2=f32
__device__ unsigned g_bar_count;
__device__ volatile unsigned g_bar_gen;

// ---------------- helpers --------------------------------------------------
__device__ __forceinline__ void ffma2(ull& d, ull a, ull b) {
    asm("fma.rn.f32x2 %0, %1, %2, %3;" : "=l"(d) : "l"(a), "l"(b), "l"(d));
}
__device__ __forceinline__ ull pack2(float x) {
    ull r; asm("mov.b64 %0, {%1, %1};" : "=l"(r) : "f"(x)); return r;
}
__device__ __forceinline__ float sigf(float x) {
    return 1.f / (1.f + __expf(-x));
}

// ---------------- resets dtype detector ------------------------------------
__global__ void detect_kernel(const unsigned* __restrict__ w) {
    __shared__ int s;
    if (threadIdx.x == 0) s = 0;
    __syncthreads();
    int f = 0;
    for (int i = threadIdx.x; i < (TT*BB/4); i += blockDim.x) {
        unsigned v = w[i];
        if (v == 0x3F800000u) f |= 2;     // float 1.0 present -> f32
        else if (v > 1u)      f |= 1;     // bytes packed (e.g. 0x0100) -> u8
    }
    if (f) atomicOr(&s, f);
    __syncthreads();
    if (threadIdx.x == 0)
        g_kind = (s & 2) ? 2 : ((s & 1) ? 1 : 0);
}

// ---------------- xW = ins @ Wi + bi  (M=65536, K=512, N=1536) -------------
__global__ __launch_bounds__(256) void gemm_xw_kernel(
    const float* __restrict__ A,    // [M,512]
    const float* __restrict__ Wi,   // [512,1536]
    const float* __restrict__ bi)   // [1536]
{
    __shared__ float As[8*128];     // transposed: As[k][m]
    __shared__ float Bs[8*128];     // Bs[k][n]
    const int tid = threadIdx.x;
    const int m0 = blockIdx.y * 128;
    const int n0 = blockIdx.x * 128;
    const int tx = tid & 15, ty = tid >> 4;

    ull acc[8][4];
    #pragma unroll
    for (int i = 0; i < 8; i++)
        #pragma unroll
        for (int j = 0; j < 4; j++) acc[i][j] = 0ull;

    const int arow = tid >> 1, ac4 = (tid & 1) * 4;
    const int brow = tid >> 5, bc4 = (tid & 31) * 4;

    for (int k0 = 0; k0 < HH; k0 += 8) {
        float4 av = *(const float4*)&A[(size_t)(m0 + arow)*HH + k0 + ac4];
        float4 bv = *(const float4*)&Wi[(size_t)(k0 + brow)*GG + n0 + bc4];
        As[(ac4+0)*128 + arow] = av.x;
        As[(ac4+1)*128 + arow] = av.y;
        As[(ac4+2)*128 + arow] = av.z;
        As[(ac4+3)*128 + arow] = av.w;
        *(float4*)&Bs[brow*128 + bc4] = bv;
        __syncthreads();
        #pragma unroll
        for (int kk = 0; kk < 8; kk++) {
            float4 a0 = *(const float4*)&As[kk*128 + ty*8];
            float4 a1 = *(const float4*)&As[kk*128 + ty*8 + 4];
            ull ap[8];
            ap[0]=pack2(a0.x); ap[1]=pack2(a0.y); ap[2]=pack2(a0.z); ap[3]=pack2(a0.w);
            ap[4]=pack2(a1.x); ap[5]=pack2(a1.y); ap[6]=pack2(a1.z); ap[7]=pack2(a1.w);
            ull b2[4];
            #pragma unroll
            for (int j = 0; j < 4; j++)
                b2[j] = *(const ull*)&Bs[kk*128 + tx*8 + 2*j];
            #pragma unroll
            for (int i = 0; i < 8; i++)
                #pragma unroll
                for (int j = 0; j < 4; j++)
                    ffma2(acc[i][j], ap[i], b2[j]);
        }
        __syncthreads();
    }

    #pragma unroll
    for (int i = 0; i < 8; i++) {
        size_t row = (size_t)(m0 + ty*8 + i);
        #pragma unroll
        for (int j = 0; j < 4; j++) {
            int col = n0 + tx*8 + 2*j;
            float2 c = *(float2*)&acc[i][j];
            float2 o;
            o.x = c.x + bi[col];
            o.y = c.y + bi[col+1];
            *(float2*)&g_xW[row*GG + col] = o;
        }
    }
}

// ---------------- persistent GRU scan --------------------------------------
#define SCAN_GRID    128
#define SCAN_THREADS 256
// smem: w_s 256*32 = 8192 floats; h_s 128*66 = 8448 floats; keep_s 128 floats
#define SMEM_FLOATS  (8192 + 8448 + 128)
#define SMEM_BYTES   (SMEM_FLOATS * 4)

__global__ __launch_bounds__(SCAN_THREADS) void scan_kernel(
    const void*  __restrict__ resets,
    const float* __restrict__ Wh,     // [512,1536]
    const float* __restrict__ b_hn,   // [512]
    float* __restrict__ out)          // [T,B,H]  (doubles as h state)
{
    extern __shared__ float sm[];
    float* w_s    = sm;                    // [k2][cg][s][kk] : k2*32+cg*16+s*2+kk
    float* h_s    = sm + 8192;             // [b][66] local-chunk k
    float* keep_s = sm + 8192 + 8448;      // [b] 0/1 keep mask

    const int tid = threadIdx.x;
    const int b   = tid & 127;
    const int cg  = tid >> 7;              // 0/1: which column pair
    const int c0  = blockIdx.x * 4;        // this CTA's 4 hidden columns
    const int ca  = c0 + 2*cg;             // this thread's first column
    const int kind = g_kind;

    // load Wh slice once: resident for the whole scan
    for (int idx = tid; idx < 512*12; idx += SCAN_THREADS) {
        int k    = idx / 12;
        int s12  = idx - k*12;
        int cgi  = s12 / 6;
        int s    = s12 - cgi*6;            // 0..5 : (r0,r1,z0,z1,n0,n1)
        int gate = s >> 1;
        int col  = c0 + 2*cgi + (s & 1);
        w_s[(k >> 1)*32 + cgi*16 + s*2 + (k & 1)] = Wh[(size_t)k*GG + gate*HH + col];
    }

    unsigned bargen = 0;
    if (tid == 0) bargen = g_bar_gen;

    float2 bh = *(const float2*)&b_hn[ca];
    __syncthreads();

    for (int t = 0; t < TT; t++) {
        // per-batch keep mask for this step
        if (tid < 128) {
            int ii = t*BB + tid;
            bool rs;
            if (kind == 2)      rs = ((const float*)resets)[ii] != 0.f;
            else if (kind == 1) rs = ((const unsigned char*)resets)[ii] != 0;
            else                rs = ((const int*)resets)[ii] != 0;
            keep_s[tid] = (t > 0 && !rs) ? 1.f : 0.f;
        }
        if (t == 0) {
            for (int i = tid; i < 128*66; i += SCAN_THREADS) h_s[i] = 0.f;
        }
        __syncthreads();

        ull acc[6];
        #pragma unroll
        for (int s = 0; s < 6; s++) acc[s] = 0ull;
        float2 hin = make_float2(0.f, 0.f);
        const float* hprev = out + (size_t)(t - 1)*BB*HH;   // only deref if t>0

        for (int c8 = 0; c8 < 8; c8++) {
            const int kb = c8 * 64;
            if (t > 0) {
                #pragma unroll
                for (int r = 0; r < 8; r++) {
                    int flat = r*256 + tid;        // 0..2047
                    int bb2  = flat >> 4;
                    int f4   = flat & 15;
                    float4 v = __ldcg((const float4*)&hprev[(size_t)bb2*HH + kb + f4*4]);
                    float kp = keep_s[bb2];
                    float* d = &h_s[bb2*66 + f4*4];
                    d[0] = v.x*kp; d[1] = v.y*kp; d[2] = v.z*kp; d[3] = v.w*kp;
                }
            }
            __syncthreads();

            if ((ca >> 6) == c8)
                hin = *(const float2*)&h_s[b*66 + (ca & 63)];

            const ull* hrow  = (const ull*)&h_s[b*66];
            const ull* wbase = (const ull*)w_s + (size_t)(kb >> 1)*16 + cg*8;
            #pragma unroll 8
            for (int k2 = 0; k2 < 32; k2++) {
                ull hp = hrow[k2];
                const ull* wp = wbase + k2*16;
                ffma2(acc[0], hp, wp[0]);
                ffma2(acc[1], hp, wp[1]);
                ffma2(acc[2], hp, wp[2]);
                ffma2(acc[3], hp, wp[3]);
                ffma2(acc[4], hp, wp[4]);
                ffma2(acc[5], hp, wp[5]);
            }
            __syncthreads();
        }

        float2 a0 = *(float2*)&acc[0], a1 = *(float2*)&acc[1];
        float2 a2 = *(float2*)&acc[2], a3 = *(float2*)&acc[3];
        float2 a4 = *(float2*)&acc[4], a5 = *(float2*)&acc[5];
        float hr0 = a0.x + a0.y, hr1 = a1.x + a1.y;
        float hz0 = a2.x + a2.y, hz1 = a3.x + a3.y;
        float hn0 = a4.x + a4.y, hn1 = a5.x + a5.y;

        const float* xwp = g_xW + ((size_t)t*BB + b)*GG + ca;
        float2 xr = *(const float2*)&xwp[0];
        float2 xz = *(const float2*)&xwp[512];
        float2 xn = *(const float2*)&xwp[1024];

        float r0 = sigf(xr.x + hr0), r1 = sigf(xr.y + hr1);
        float z0 = sigf(xz.x + hz0), z1 = sigf(xz.y + hz1);
        float n0 = tanhf(xn.x + r0*(hn0 + bh.x));
        float n1 = tanhf(xn.y + r1*(hn1 + bh.y));

        float2 o;
        o.x = (1.f - z0)*n0 + z0*hin.x;
        o.y = (1.f - z1)*n1 + z1*hin.y;
        __stcg((float2*)&out[((size_t)t*BB + b)*HH + ca], o);

        // grid-wide barrier (sense-reversing, all 128 CTAs co-resident)
        __threadfence();
        __syncthreads();
        if (tid == 0) {
            if (atomicAdd(&g_bar_count, 1u) == (unsigned)(SCAN_GRID - 1)) {
                atomicExch(&g_bar_count, 0u);
                __threadfence();
                g_bar_gen = bargen + 1;
            } else {
                while (g_bar_gen == bargen) __nanosleep(32);
                __threadfence();
            }
            bargen++;
        }
        __syncthreads();
    }
}

// ---------------- launcher -------------------------------------------------
extern "C" void kernel_launch(void* const* d_in, const int* in_sizes, int n_in,
                              void* d_out, int out_size) {
    const float* ins    = (const float*)d_in[0];
    const void*  resets = d_in[1];
    const float* Wi     = (const float*)d_in[2];
    const float* bi     = (const float*)d_in[3];
    const float* Wh     = (const float*)d_in[4];
    const float* b_hn   = (const float*)d_in[5];
    float* out = (float*)d_out;

    cudaFuncSetAttribute(scan_kernel,
                         cudaFuncAttributeMaxDynamicSharedMemorySize, SMEM_BYTES);

    detect_kernel<<<1, 256>>>((const unsigned*)resets);
    gemm_xw_kernel<<<dim3(GG/128, (TT*BB)/128), 256>>>(ins, Wi, bi);
    scan_kernel<<<SCAN_GRID, SCAN_THREADS, SMEM_BYTES>>>(resets, Wh, b_hn, out);
}

// round 3
// speedup vs baseline: 1.2291x; 1.2291x over previous
#include <cuda_runtime.h>
#include <cstdint>

#define TT 512
#define BB 128
#define HH 512
#define GG (3*HH)   // 1536

typedef unsigned long long ull;

// ---------------- device globals (scratch; no cudaMalloc allowed) ----------
__device__ float    g_xW[(size_t)TT*BB*GG];   // [T,B,3H] input-side projections
__device__ float    g_h[2][BB*HH];            // ping-pong keep-masked hidden state
__device__ int      g_kind;                   // resets dtype: 0=i32, 1=u8, 2=f32
__device__ unsigned g_bar_count;
__device__ volatile unsigned g_bar_gen;

// ---------------- helpers --------------------------------------------------
__device__ __forceinline__ void ffma2(ull& d, ull a, ull b) {
    asm("fma.rn.f32x2 %0, %1, %2, %3;" : "=l"(d) : "l"(a), "l"(b), "l"(d));
}
__device__ __forceinline__ ull pack2(float x) {
    ull r; asm("mov.b64 %0, {%1, %1};" : "=l"(r) : "f"(x)); return r;
}
__device__ __forceinline__ float sigf(float x) {
    return 1.f / (1.f + __expf(-x));
}

// ---------------- resets dtype detector ------------------------------------
__global__ void detect_kernel(const unsigned* __restrict__ w) {
    __shared__ int s;
    if (threadIdx.x == 0) s = 0;
    __syncthreads();
    int f = 0;
    for (int i = threadIdx.x; i < (TT*BB/4); i += blockDim.x) {
        unsigned v = w[i];
        if (v == 0x3F800000u) f |= 2;     // float 1.0 present -> f32
        else if (v > 1u)      f |= 1;     // bytes packed (e.g. 0x0100) -> u8
    }
    if (f) atomicOr(&s, f);
    __syncthreads();
    if (threadIdx.x == 0)
        g_kind = (s & 2) ? 2 : ((s & 1) ? 1 : 0);
}

// ---------------- xW = ins @ Wi + bi  (M=65536, K=512, N=1536) -------------
__global__ __launch_bounds__(256, 2) void gemm_xw_kernel(
    const float* __restrict__ A,    // [M,512]
    const float* __restrict__ Wi,   // [512,1536]
    const float* __restrict__ bi)   // [1536]
{
    __shared__ ull   As64[8*128];   // A duplicated into both f32x2 lanes: [k][m]
    __shared__ float Bs[8*128];     // [k][n]
    const int tid = threadIdx.x;
    const int m0 = blockIdx.y * 128;
    const int n0 = blockIdx.x * 128;
    const int tx = tid & 15, ty = tid >> 4;

    ull acc[8][4];
    #pragma unroll
    for (int i = 0; i < 8; i++)
        #pragma unroll
        for (int j = 0; j < 4; j++) acc[i][j] = 0ull;

    const int arow = tid >> 1, ac4 = (tid & 1) * 4;
    const int brow = tid >> 5, bc4 = (tid & 31) * 4;

    const unsigned as_base = (unsigned)__cvta_generic_to_shared(As64);
    const unsigned bs_base = (unsigned)__cvta_generic_to_shared(Bs);

    for (int k0 = 0; k0 < HH; k0 += 8) {
        float4 av = *(const float4*)&A[(size_t)(m0 + arow)*HH + k0 + ac4];
        float4 bv = *(const float4*)&Wi[(size_t)(k0 + brow)*GG + n0 + bc4];
        As64[(ac4+0)*128 + arow] = pack2(av.x);
        As64[(ac4+1)*128 + arow] = pack2(av.y);
        As64[(ac4+2)*128 + arow] = pack2(av.z);
        As64[(ac4+3)*128 + arow] = pack2(av.w);
        *(float4*)&Bs[brow*128 + bc4] = bv;
        __syncthreads();
        #pragma unroll
        for (int kk = 0; kk < 8; kk++) {
            ull ap[8];
            #pragma unroll
            for (int p = 0; p < 4; p++) {
                unsigned a = as_base + (unsigned)((kk*128 + ty*8 + 2*p) * 8);
                asm volatile("ld.shared.v2.u64 {%0,%1},[%2];"
                             : "=l"(ap[2*p]), "=l"(ap[2*p+1]) : "r"(a));
            }
            ull b2[4];
            #pragma unroll
            for (int p = 0; p < 2; p++) {
                unsigned a = bs_base + (unsigned)((kk*128 + tx*8) * 4 + p*16);
                asm volatile("ld.shared.v2.u64 {%0,%1},[%2];"
                             : "=l"(b2[2*p]), "=l"(b2[2*p+1]) : "r"(a));
            }
            #pragma unroll
            for (int i = 0; i < 8; i++)
                #pragma unroll
                for (int j = 0; j < 4; j++)
                    ffma2(acc[i][j], ap[i], b2[j]);
        }
        __syncthreads();
    }

    #pragma unroll
    for (int i = 0; i < 8; i++) {
        size_t row = (size_t)(m0 + ty*8 + i);
        #pragma unroll
        for (int j = 0; j < 4; j++) {
            int col = n0 + tx*8 + 2*j;
            float2 c = *(float2*)&acc[i][j];
            float2 o;
            o.x = c.x + bi[col];
            o.y = c.y + bi[col+1];
            *(float2*)&g_xW[row*GG + col] = o;
        }
    }
}

// ---------------- persistent GRU scan --------------------------------------
#define SCAN_GRID    128
#define SCAN_THREADS 256
// smem: h double-buffer 2*128*64 floats = 64KB, weights 12*512 floats = 24KB
#define SMEM_W_OFF   65536
#define SMEM_BYTES   (65536 + 24576)

// stage one 64-k chunk of h: g_h layout [b][512] -> swizzled smem [b][16 segs]
__device__ __forceinline__ void stage_chunk(const float* gsrc, unsigned sdst, int tid) {
    #pragma unroll
    for (int r = 0; r < 8; r++) {
        int idx = r*256 + tid;          // 0..2047
        int bb  = idx >> 4;
        int seg = idx & 15;
        const float* src = gsrc + bb*512 + seg*4;
        unsigned dst = sdst + (unsigned)(bb*256 + ((seg ^ (bb & 15)) << 4));
        asm volatile("cp.async.cg.shared.global [%0], [%1], 16;" :: "r"(dst), "l"(src));
    }
}

__device__ __forceinline__ void gridbar(int tid, unsigned& bargen) {
    __threadfence();
    __syncthreads();
    if (tid == 0) {
        if (atomicAdd(&g_bar_count, 1u) == (unsigned)(SCAN_GRID - 1)) {
            atomicExch(&g_bar_count, 0u);
            __threadfence();
            g_bar_gen = bargen + 1;
        } else {
            while (g_bar_gen == bargen) __nanosleep(32);
            __threadfence();
        }
        bargen++;
    }
    __syncthreads();
}

__global__ __launch_bounds__(SCAN_THREADS, 1) void scan_kernel(
    const void*  __restrict__ resets,
    const float* __restrict__ Wh,     // [512,1536]
    const float* __restrict__ b_hn,   // [512]
    float* __restrict__ out)          // [T,B,H]
{
    extern __shared__ float sm[];
    const unsigned smem_base = (unsigned)__cvta_generic_to_shared(sm);
    float* w_f = sm + (SMEM_W_OFF/4);

    const int tid = threadIdx.x;
    const int b   = tid & 127;
    const int cg  = tid >> 7;              // 0/1: which column pair
    const int c0  = blockIdx.x * 4;        // this CTA's 4 hidden columns
    const int ca  = c0 + 2*cg;             // this thread's first column
    const int bx  = b & 15;
    const int kind = g_kind;

    // zero the t=0 state buffer (grid-strided; visible after first gridbar)
    {
        int gidx = blockIdx.x * SCAN_THREADS + tid;   // 0..32767
        *(float2*)&g_h[0][gidx*2] = make_float2(0.f, 0.f);
    }

    // load this CTA's Wh slice: w_f[out12][k], out12 = cg*6 + gate*2 + j
    for (int idx = tid; idx < 12*512; idx += SCAN_THREADS) {
        int o12 = idx >> 9;
        int k   = idx & 511;
        int cgi = o12 / 6, o = o12 % 6;
        int g = o >> 1, j = o & 1;
        w_f[o12*512 + k] = Wh[(size_t)k*GG + g*HH + c0 + cgi*2 + j];
    }

    unsigned bargen = 0;
    if (tid == 0) bargen = g_bar_gen;
    float2 bh = *(const float2*)&b_hn[ca];

    const unsigned h_smem = smem_base;
    const unsigned wrow_base = smem_base + SMEM_W_OFF + (unsigned)(cg*6*512*4);

    gridbar(tid, bargen);   // zeros of g_h[0] now visible everywhere

    for (int t = 0; t < TT; t++) {
        const float* hsrc = g_h[t & 1];

        // prefetch input-side projections + next-step keep mask (latency hidden by chunk loop)
        const float* xwp = g_xW + ((size_t)t*BB + b)*GG + ca;
        float2 xr = __ldcg((const float2*)(xwp));
        float2 xz = __ldcg((const float2*)(xwp + 512));
        float2 xn = __ldcg((const float2*)(xwp + 1024));
        float keepn = 0.f;
        if (t + 1 < TT) {
            int ii = (t+1)*BB + b;
            bool rs;
            if (kind == 2)      rs = ((const float*)resets)[ii] != 0.f;
            else if (kind == 1) rs = ((const unsigned char*)resets)[ii] != 0;
            else                rs = ((const int*)resets)[ii] != 0;
            keepn = rs ? 0.f : 1.f;
        }

        stage_chunk(hsrc, h_smem, tid);
        asm volatile("cp.async.commit_group;");

        ull acc[6];
        #pragma unroll
        for (int s = 0; s < 6; s++) acc[s] = 0ull;
        float2 hin = make_float2(0.f, 0.f);

        for (int c8 = 0; c8 < 8; c8++) {
            if (c8 < 7) {
                stage_chunk(hsrc + (c8+1)*64, h_smem + (unsigned)(((c8+1)&1)*32768), tid);
                asm volatile("cp.async.commit_group;");
                asm volatile("cp.async.wait_group 1;");
            } else {
                asm volatile("cp.async.wait_group 0;");
            }
            __syncthreads();

            const unsigned hrow = h_smem + (unsigned)((c8&1)*32768 + b*256);
            if ((ca >> 6) == c8) {
                int seg = (ca & 63) >> 2;
                int w   = (c8&1)*8192 + b*64 + ((seg ^ bx) << 2) + (ca & 3);
                hin = *(float2*)&sm[w];
            }
            const unsigned wr = wrow_base + (unsigned)(c8*256);

            #pragma unroll
            for (int k4 = 0; k4 < 16; k4++) {
                ull h01, h23;
                asm volatile("ld.shared.v2.u64 {%0,%1},[%2];"
                             : "=l"(h01), "=l"(h23) : "r"(hrow + (unsigned)((k4 ^ bx) << 4)));
                #pragma unroll
                for (int o = 0; o < 6; o++) {
                    ull w01, w23;
                    asm volatile("ld.shared.v2.u64 {%0,%1},[%2];"
                                 : "=l"(w01), "=l"(w23) : "r"(wr + (unsigned)(o*2048 + (k4<<4))));
                    ffma2(acc[o], h01, w01);
                    ffma2(acc[o], h23, w23);
                }
            }
            __syncthreads();
        }

        float2 a0 = *(float2*)&acc[0], a1 = *(float2*)&acc[1];
        float2 a2 = *(float2*)&acc[2], a3 = *(float2*)&acc[3];
        float2 a4 = *(float2*)&acc[4], a5 = *(float2*)&acc[5];
        float hr0 = a0.x + a0.y, hr1 = a1.x + a1.y;
        float hz0 = a2.x + a2.y, hz1 = a3.x + a3.y;
        float hn0 = a4.x + a4.y, hn1 = a5.x + a5.y;

        float r0 = sigf(xr.x + hr0), r1 = sigf(xr.y + hr1);
        float z0 = sigf(xz.x + hz0), z1 = sigf(xz.y + hz1);
        float n0 = tanhf(xn.x + r0*(hn0 + bh.x));
        float n1 = tanhf(xn.y + r1*(hn1 + bh.y));

        float2 o;
        o.x = (1.f - z0)*n0 + z0*hin.x;
        o.y = (1.f - z1)*n1 + z1*hin.y;
        __stcg((float2*)&out[((size_t)t*BB + b)*HH + ca], o);
        if (t + 1 < TT)
            *(float2*)&g_h[(t+1)&1][b*512 + ca] = make_float2(o.x*keepn, o.y*keepn);

        gridbar(tid, bargen);
    }
}

// ---------------- launcher -------------------------------------------------
extern "C" void kernel_launch(void* const* d_in, const int* in_sizes, int n_in,
                              void* d_out, int out_size) {
    const float* ins    = (const float*)d_in[0];
    const void*  resets = d_in[1];
    const float* Wi     = (const float*)d_in[2];
    const float* bi     = (const float*)d_in[3];
    const float* Wh     = (const float*)d_in[4];
    const float* b_hn   = (const float*)d_in[5];
    float* out = (float*)d_out;

    cudaFuncSetAttribute(scan_kernel,
                         cudaFuncAttributeMaxDynamicSharedMemorySize, SMEM_BYTES);

    detect_kernel<<<1, 256>>>((const unsigned*)resets);
    gemm_xw_kernel<<<dim3(GG/128, (TT*BB)/128), 256>>>(ins, Wi, bi);
    scan_kernel<<<SCAN_GRID, SCAN_THREADS, SMEM_BYTES>>>(resets, Wh, b_hn, out);
}

// round 5
// speedup vs baseline: 1.2933x; 1.0522x over previous
#include <cuda_runtime.h>
#include <cstdint>

#define TT 512
#define BB 128
#define HH 512
#define GG (3*HH)   // 1536
#define NBP (BB/2)  // 64 b-pairs

typedef unsigned long long ull;

// ---------------- device globals (scratch; no cudaMalloc allowed) ----------
__device__ float g_xW[(size_t)TT*BB*GG];     // [T,B,3H] input-side projections
// h ping-pong, layout: unit(k2, bp) = 16B {h[2bp][2k2], h[2bp+1][2k2], h[2bp][2k2+1], h[2bp+1][2k2+1]}
__device__ float g_h2[2][(HH/2)*NBP*4];
__device__ int   g_flags[BB];                // per-CTA publish counters
__device__ int   g_kind;                     // resets dtype: 0=i32, 1=u8, 2=f32

// ---------------- helpers --------------------------------------------------
__device__ __forceinline__ void ffma2(ull& d, ull a, ull b) {
    asm("fma.rn.f32x2 %0, %1, %2, %3;" : "=l"(d) : "l"(a), "l"(b), "l"(d));
}
__device__ __forceinline__ ull fadd2(ull a, ull b) {
    ull d; asm("add.rn.f32x2 %0, %1, %2;" : "=l"(d) : "l"(a), "l"(b)); return d;
}
__device__ __forceinline__ ull pack2(float x) {
    ull r; asm("mov.b64 %0, {%1, %1};" : "=l"(r) : "f"(x)); return r;
}
__device__ __forceinline__ float sigf(float x) { return 1.f / (1.f + __expf(-x)); }

// ---------------- resets dtype detector + flag reset ------------------------
__global__ void detect_kernel(const unsigned* __restrict__ w) {
    __shared__ int s;
    if (threadIdx.x == 0) s = 0;
    __syncthreads();
    int f = 0;
    for (int i = threadIdx.x; i < (TT*BB/4); i += blockDim.x) {
        unsigned v = w[i];
        if (v == 0x3F800000u) f |= 2;     // float 1.0 present -> f32
        else if (v > 1u)      f |= 1;     // packed bytes -> u8
    }
    if (f) atomicOr(&s, f);
    if (threadIdx.x < BB) g_flags[threadIdx.x] = 0;   // reset barrier flags each run
    __syncthreads();
    if (threadIdx.x == 0)
        g_kind = (s & 2) ? 2 : ((s & 1) ? 1 : 0);
}

// ---------------- xW = ins @ Wi + bi  (M=65536, K=512, N=1536) -------------
// 128x128x8 tiles, register double-buffered staging, f32x2 paired over M.
__global__ __launch_bounds__(256, 2) void gemm_xw_kernel(
    const float* __restrict__ A,    // [M,512]
    const float* __restrict__ Wi,   // [512,1536]
    const float* __restrict__ bi)   // [1536]
{
    __shared__ float As[2][8][128];     // [k][m]
    __shared__ ull   Bs[2][8][8][16];   // [k][j][tx] pre-duplicated f32x2
    const int tid = threadIdx.x;
    const int m0 = blockIdx.y * 128;
    const int n0 = blockIdx.x * 128;
    const int tx = tid & 15, ty = tid >> 4;

    const int arow = tid >> 1, ac4 = (tid & 1) * 4;
    const int brow = tid >> 5, bc4 = (tid & 31) * 4;

    ull acc[4][8];
    #pragma unroll
    for (int i = 0; i < 4; i++)
        #pragma unroll
        for (int j = 0; j < 8; j++) acc[i][j] = 0ull;

    float4 av = *(const float4*)&A[(size_t)(m0 + arow)*HH + ac4];
    float4 bv = *(const float4*)&Wi[(size_t)brow*GG + n0 + bc4];

    for (int k0 = 0; k0 < HH; k0 += 8) {
        const int p = (k0 >> 3) & 1;
        As[p][ac4+0][arow] = av.x;
        As[p][ac4+1][arow] = av.y;
        As[p][ac4+2][arow] = av.z;
        As[p][ac4+3][arow] = av.w;
        {   // scatter B into [k][n&7][n>>3], duplicated
            float vals[4] = {bv.x, bv.y, bv.z, bv.w};
            #pragma unroll
            for (int j = 0; j < 4; j++) {
                int n = bc4 + j;
                Bs[p][brow][n & 7][n >> 3] = pack2(vals[j]);
            }
        }
        __syncthreads();
        if (k0 + 8 < HH) {
            av = *(const float4*)&A[(size_t)(m0 + arow)*HH + k0 + 8 + ac4];
            bv = *(const float4*)&Wi[(size_t)(k0 + 8 + brow)*GG + n0 + bc4];
        }
        #pragma unroll
        for (int kk = 0; kk < 8; kk++) {
            ull a2[4];
            #pragma unroll
            for (int mp = 0; mp < 4; mp++)
                a2[mp] = *(const ull*)&As[p][kk][ty*8 + 2*mp];
            ull b2[8];
            #pragma unroll
            for (int j = 0; j < 8; j++)
                b2[j] = Bs[p][kk][j][tx];
            #pragma unroll
            for (int mp = 0; mp < 4; mp++)
                #pragma unroll
                for (int j = 0; j < 8; j++)
                    ffma2(acc[mp][j], a2[mp], b2[j]);
        }
        __syncthreads();
    }

    #pragma unroll
    for (int mp = 0; mp < 4; mp++) {
        size_t r0 = (size_t)(m0 + ty*8 + 2*mp);
        #pragma unroll
        for (int j = 0; j < 8; j++) {
            int col = n0 + tx*8 + j;
            float2 c = *(float2*)&acc[mp][j];
            float bb = bi[col];
            g_xW[r0*GG + col]     = c.x + bb;
            g_xW[(r0+1)*GG + col] = c.y + bb;
        }
    }
}

// ---------------- persistent GRU scan --------------------------------------
#define SCAN_GRID    128
#define SCAN_THREADS 256
// smem: weights 12*512 ull = 48KB, partials 8*64*12 ull = 48KB
#define SMEM_W_ULLS   (12*512)
#define SMEM_P_ULLS   (8*64*12)
#define SMEM_BYTES    ((SMEM_W_ULLS + SMEM_P_ULLS) * 8)

__global__ __launch_bounds__(SCAN_THREADS, 1) void scan_kernel(
    const void*  __restrict__ resets,
    const float* __restrict__ Wh,     // [512,1536]
    const float* __restrict__ b_hn,   // [512]
    float* __restrict__ out)          // [T,B,H]
{
    extern __shared__ ull smu[];
    ull* wsm  = smu;                   // [o12][k512] duplicated f32x2 weights
    ull* part = smu + SMEM_W_ULLS;     // [w8][bp64][o12]

    const int tid = threadIdx.x;
    const int bid = blockIdx.x;
    const int c0  = bid * 4;           // this CTA's 4 hidden columns
    // main-loop role
    const int w   = tid >> 5;          // k-slice 0..7  (k in [w*64, w*64+64))
    const int l   = tid & 31;          // bp_a = l, bp_b = l+32
    // epilogue role
    const int ebp = tid >> 2;          // 0..63
    const int ecl = tid & 3;           // 0..3
    const int cg  = c0 + ecl;          // global column
    const int b0  = 2*ebp, b1 = 2*ebp + 1;
    const int kind = g_kind;

    // zero h(0): full buffer = 32768 ull; 128 CTAs x 256 threads x 1 ull
    ((ull*)g_h2[0])[bid*SCAN_THREADS + tid] = 0ull;

    // load + duplicate this CTA's Wh slice: wsm[o][k], o = col*3 + gate
    for (int i = tid; i < 12*512; i += SCAN_THREADS) {
        int o = i >> 9, k = i & 511;
        int col = o / 3, g = o - col*3;
        wsm[(size_t)o*512 + k] = pack2(Wh[(size_t)k*GG + g*HH + c0 + col]);
    }

    const float bhn = b_hn[cg];

    __threadfence();
    __syncthreads();
    if (tid == 0) __stcg(&g_flags[bid], 1);   // h(0) published

    for (int t = 0; t < TT; t++) {
        // ---- wait for all CTAs to publish h(t) ----
        if (tid < 32) {
            const int4* fp = (const int4*)g_flags;
            int need = t + 1;
            for (;;) {
                int4 f = __ldcg(&fp[tid]);
                bool ok = (f.x >= need) & (f.y >= need) & (f.z >= need) & (f.w >= need);
                if (__all_sync(0xFFFFFFFFu, ok)) break;
                __nanosleep(20);
            }
        }
        __syncthreads();

        // ---- epilogue-role prefetches (overlap with main loop) ----
        const float* xwp0 = g_xW + ((size_t)t*BB + b0)*GG + cg;
        float xr0 = __ldcg(xwp0),        xr1 = __ldcg(xwp0 + GG);
        float xz0 = __ldcg(xwp0 + 512),  xz1 = __ldcg(xwp0 + GG + 512);
        float xn0 = __ldcg(xwp0 + 1024), xn1 = __ldcg(xwp0 + GG + 1024);
        const ull* hbuf = (const ull*)g_h2[t & 1];
        ull hin2 = __ldcg(&hbuf[((size_t)(cg >> 1)*NBP + ebp)*2 + (cg & 1)]);
        float keep0 = 0.f, keep1 = 0.f;
        if (t + 1 < TT) {
            int ii = (t+1)*BB;
            bool r0s, r1s;
            if (kind == 2) {
                r0s = ((const float*)resets)[ii+b0] != 0.f;
                r1s = ((const float*)resets)[ii+b1] != 0.f;
            } else if (kind == 1) {
                r0s = ((const unsigned char*)resets)[ii+b0] != 0;
                r1s = ((const unsigned char*)resets)[ii+b1] != 0;
            } else {
                r0s = ((const int*)resets)[ii+b0] != 0;
                r1s = ((const int*)resets)[ii+b1] != 0;
            }
            keep0 = r0s ? 0.f : 1.f;
            keep1 = r1s ? 0.f : 1.f;
        }

        // ---- main loop: this warp's 64-k slice, all 12 outputs, 4 b's ----
        ull acc_a[12], acc_b[12];
        #pragma unroll
        for (int o = 0; o < 12; o++) { acc_a[o] = 0ull; acc_b[o] = 0ull; }

        const uint4* hp = (const uint4*)g_h2[t & 1] + (size_t)w*32*NBP + l;
        const ull*   wb = wsm + (size_t)w*64;     // wsm[o*512 + w*64 + 2*k2]
        uint4 ca = __ldcg(hp);
        uint4 cb = __ldcg(hp + 32);
        #pragma unroll 8
        for (int k2 = 0; k2 < 32; k2++) {
            uint4 na, nb;
            if (k2 < 31) {
                na = __ldcg(hp + (size_t)(k2+1)*NBP);
                nb = __ldcg(hp + (size_t)(k2+1)*NBP + 32);
            }
            ull ha0 = *(ull*)&ca.x, ha1 = *(ull*)&ca.z;
            ull hb0 = *(ull*)&cb.x, hb1 = *(ull*)&cb.z;
            #pragma unroll
            for (int o = 0; o < 12; o++) {
                ull w0, w1;
                asm volatile("ld.shared.v2.u64 {%0,%1},[%2];"
                    : "=l"(w0), "=l"(w1)
                    : "r"((unsigned)__cvta_generic_to_shared(&wb[(size_t)o*512 + 2*k2])));
                ffma2(acc_a[o], ha0, w0);
                ffma2(acc_a[o], ha1, w1);
                ffma2(acc_b[o], hb0, w0);
                ffma2(acc_b[o], hb1, w1);
            }
            ca = na; cb = nb;
        }

        // ---- cross-warp K reduction through smem ----
        {
            ull* pa = &part[((size_t)w*64 + l)*12];
            ull* pb = &part[((size_t)w*64 + l + 32)*12];
            #pragma unroll
            for (int o = 0; o < 12; o++) { pa[o] = acc_a[o]; pb[o] = acc_b[o]; }
        }
        __syncthreads();

        ull hg[3];
        #pragma unroll
        for (int g = 0; g < 3; g++) {
            int o = ecl*3 + g;
            ull s = part[(size_t)ebp*12 + o];
            #pragma unroll
            for (int ww = 1; ww < 8; ww++)
                s = fadd2(s, part[((size_t)ww*64 + ebp)*12 + o]);
            hg[g] = s;
        }

        // ---- nonlinearity + write ----
        float2 hr = *(float2*)&hg[0];
        float2 hz = *(float2*)&hg[1];
        float2 hn = *(float2*)&hg[2];
        float2 hi = *(float2*)&hin2;

        float r0 = sigf(xr0 + hr.x), r1 = sigf(xr1 + hr.y);
        float z0 = sigf(xz0 + hz.x), z1 = sigf(xz1 + hz.y);
        float n0 = tanhf(xn0 + r0*(hn.x + bhn));
        float n1 = tanhf(xn1 + r1*(hn.y + bhn));
        float o0 = (1.f - z0)*n0 + z0*hi.x;
        float o1 = (1.f - z1)*n1 + z1*hi.y;

        out[((size_t)t*BB + b0)*HH + cg] = o0;
        out[((size_t)t*BB + b1)*HH + cg] = o1;

        if (t + 1 < TT) {
            float2 hw = make_float2(o0*keep0, o1*keep1);
            __stcg((ull*)&((ull*)g_h2[(t+1) & 1])[((size_t)(cg >> 1)*NBP + ebp)*2 + (cg & 1)],
                   *(ull*)&hw);
            __threadfence();
            __syncthreads();
            if (tid == 0) __stcg(&g_flags[bid], t + 2);
        } else {
            __syncthreads();
        }
    }
}

// ---------------- launcher -------------------------------------------------
extern "C" void kernel_launch(void* const* d_in, const int* in_sizes, int n_in,
                              void* d_out, int out_size) {
    const float* ins    = (const float*)d_in[0];
    const void*  resets = d_in[1];
    const float* Wi     = (const float*)d_in[2];
    const float* bi     = (const float*)d_in[3];
    const float* Wh     = (const float*)d_in[4];
    const float* b_hn   = (const float*)d_in[5];
    float* out = (float*)d_out;

    cudaFuncSetAttribute(scan_kernel,
                         cudaFuncAttributeMaxDynamicSharedMemorySize, SMEM_BYTES);

    detect_kernel<<<1, 256>>>((const unsigned*)resets);
    gemm_xw_kernel<<<dim3(GG/128, (TT*BB)/128), 256>>>(ins, Wi, bi);
    scan_kernel<<<SCAN_GRID, SCAN_THREADS, SMEM_BYTES>>>(resets, Wh, b_hn, out);
}